// round 1
// baseline (speedup 1.0000x reference)
#include <cuda_runtime.h>
#include <math.h>

#define H 128
#define MAXM 2048
#define MAXJ 8192
#define MAXN 262144
#define NB 8
#define MAIN_BLOCKS 296
#define MAIN_THREADS 128
#define RED_BLOCKS 512
#define RED_THREADS 256

// -------- device scratch (no allocation allowed) --------
__device__ float d_g[H];
__device__ float d_A[MAXM * H];
__device__ float d_B[MAXJ * H];
__device__ float d_scores[MAXN];
__device__ unsigned long long d_maxkey;
__device__ double d_psumE[RED_BLOCKS];
__device__ double d_psumS[RED_BLOCKS];

// order-preserving key for float (bigger float -> bigger uint)
__device__ __forceinline__ unsigned int fkey(float f) {
    unsigned int b = __float_as_uint(f);
    return (b & 0x80000000u) ? ~b : (b | 0x80000000u);
}

// ---------------- precompute g = x_graph @ W0[0:2H] + b0 ----------------
__global__ void k_pre_g(const float* __restrict__ xg,
                        const float* __restrict__ W0,
                        const float* __restrict__ b0) {
    __shared__ float s[2 * H];
    int t = threadIdx.x;
    if (t == 0) d_maxkey = 0ull;   // reset reduction state every replay
    s[t] = xg[t];
    s[t + H] = xg[t + H];
    __syncthreads();
    float acc = b0[t];
#pragma unroll 8
    for (int k = 0; k < 2 * H; k++) acc += s[k] * W0[k * H + t];
    d_g[t] = acc;
}

// ---------------- precompute A = x_m @ W0[2H:3H], B = x_job @ W0[3H:4H] ----------------
__global__ void k_pre_rows(const float* __restrict__ xm,
                           const float* __restrict__ xj,
                           const float* __restrict__ W0,
                           int M, int J) {
    const int blocksA = (M + 7) / 8;
    const int t = threadIdx.x;
    __shared__ float s[8][H];

    const float* src;
    float* dst;
    int row0, nrows, off;
    if ((int)blockIdx.x < blocksA) {
        row0 = blockIdx.x * 8; nrows = min(8, M - row0);
        src = xm; off = 2 * H; dst = d_A;
    } else {
        row0 = ((int)blockIdx.x - blocksA) * 8; nrows = min(8, J - row0);
        src = xj; off = 3 * H; dst = d_B;
    }
#pragma unroll
    for (int r = 0; r < 8; r++)
        s[r][t] = (r < nrows) ? src[(row0 + r) * H + t] : 0.f;
    __syncthreads();

    float acc[8];
#pragma unroll
    for (int r = 0; r < 8; r++) acc[r] = 0.f;
    const float* Wp = W0 + off * H + t;
#pragma unroll 4
    for (int k = 0; k < H; k++) {
        float w = Wp[k * H];
#pragma unroll
        for (int r = 0; r < 8; r++) acc[r] += s[r][k] * w;
    }
    for (int r = 0; r < nrows; r++) dst[(row0 + r) * H + t] = acc[r];
}

// ---------------- main: gather + layer1 + layer2 -> scores + block max ----------------
__global__ void __launch_bounds__(MAIN_THREADS)
k_main(const int* __restrict__ m_ids, const int* __restrict__ job_idx,
       const float* __restrict__ W1, const float* __restrict__ b1,
       const float* __restrict__ W2, int N) {
    extern __shared__ float smem[];
    float* W1s = smem;                 // H*H
    float* b1s = W1s + H * H;          // H
    float* w2s = b1s + H;              // H
    float* gs  = w2s + H;              // H
    float* h0s = gs + H;               // (MAIN_THREADS/32)*NB*H
    __shared__ unsigned long long wkey[MAIN_THREADS / 32];

    const int t = threadIdx.x;
    for (int i = t; i < H * H; i += blockDim.x) W1s[i] = W1[i];
    if (t < H) { b1s[t] = b1[t]; w2s[t] = W2[t]; gs[t] = d_g[t]; }
    __syncthreads();

    const int lane = t & 31;
    const int wib = t >> 5;
    const int warp = blockIdx.x * (MAIN_THREADS / 32) + wib;
    const int totalWarps = gridDim.x * (MAIN_THREADS / 32);
    float* myh0 = h0s + wib * NB * H;
    const int jb = lane * 4;

    unsigned long long wmax = 0ull;

    for (int base = warp * NB; base < N; base += totalWarps * NB) {
        const int cnt = min(NB, N - base);

        // ---- stage h0 = relu(g + A[m] + B[j]) for NB ops ----
#pragma unroll
        for (int n = 0; n < NB; n++) {
            float4 h = make_float4(0.f, 0.f, 0.f, 0.f);
            if (n < cnt) {
                int id = base + n;
                int m = m_ids[id];
                int jd = job_idx[id];
                float4 a  = *(const float4*)(d_A + m * H + jb);
                float4 b  = *(const float4*)(d_B + jd * H + jb);
                float4 g4 = *(const float4*)(gs + jb);
                h.x = fmaxf(g4.x + a.x + b.x, 0.f);
                h.y = fmaxf(g4.y + a.y + b.y, 0.f);
                h.z = fmaxf(g4.z + a.z + b.z, 0.f);
                h.w = fmaxf(g4.w + a.w + b.w, 0.f);
            }
            *(float4*)(myh0 + n * H + jb) = h;
        }
        __syncwarp();

        // ---- layer1: acc[n][jj] = h0[n] . W1[:, jb+jj] ----
        float acc0[NB], acc1[NB], acc2[NB], acc3[NB];
#pragma unroll
        for (int n = 0; n < NB; n++) { acc0[n] = 0.f; acc1[n] = 0.f; acc2[n] = 0.f; acc3[n] = 0.f; }

#pragma unroll 2
        for (int k = 0; k < H; k += 4) {
            float4 wa = *(const float4*)(W1s + (k + 0) * H + jb);
            float4 wb = *(const float4*)(W1s + (k + 1) * H + jb);
            float4 wc = *(const float4*)(W1s + (k + 2) * H + jb);
            float4 wd = *(const float4*)(W1s + (k + 3) * H + jb);
#pragma unroll
            for (int n = 0; n < NB; n++) {
                float4 h = *(const float4*)(myh0 + n * H + k);
                acc0[n] += h.x * wa.x; acc0[n] += h.y * wb.x; acc0[n] += h.z * wc.x; acc0[n] += h.w * wd.x;
                acc1[n] += h.x * wa.y; acc1[n] += h.y * wb.y; acc1[n] += h.z * wc.y; acc1[n] += h.w * wd.y;
                acc2[n] += h.x * wa.z; acc2[n] += h.y * wb.z; acc2[n] += h.z * wc.z; acc2[n] += h.w * wd.z;
                acc3[n] += h.x * wa.w; acc3[n] += h.y * wb.w; acc3[n] += h.z * wc.w; acc3[n] += h.w * wd.w;
            }
        }

        // ---- layer2: relu + dot with w2, warp-reduce -> score ----
#pragma unroll
        for (int n = 0; n < NB; n++) {
            if (n >= cnt) break;
            float t0 = fmaxf(acc0[n] + b1s[jb + 0], 0.f);
            float t1 = fmaxf(acc1[n] + b1s[jb + 1], 0.f);
            float t2 = fmaxf(acc2[n] + b1s[jb + 2], 0.f);
            float t3 = fmaxf(acc3[n] + b1s[jb + 3], 0.f);
            float p = t0 * w2s[jb + 0] + t1 * w2s[jb + 1] + t2 * w2s[jb + 2] + t3 * w2s[jb + 3];
#pragma unroll
            for (int off = 16; off > 0; off >>= 1)
                p += __shfl_down_sync(0xffffffffu, p, off);
            if (lane == 0) {
                d_scores[base + n] = p;
                unsigned long long key =
                    ((unsigned long long)fkey(p) << 32) |
                    (unsigned long long)(~(unsigned int)(base + n));
                if (key > wmax) wmax = key;
            }
        }
        __syncwarp();
    }

    if (lane == 0) wkey[wib] = wmax;
    __syncthreads();
    if (t == 0) {
        unsigned long long k = wkey[0];
#pragma unroll
        for (int w = 1; w < MAIN_THREADS / 32; w++) k = max(k, wkey[w]);
        atomicMax(&d_maxkey, k);
    }
}

// ---------------- pass 2: partial sums of exp(s - max) and s*exp(s - max) ----------------
__global__ void k_sums(int N) {
    unsigned long long key = d_maxkey;
    unsigned int hi = (unsigned int)(key >> 32);
    float gmax = __uint_as_float((hi & 0x80000000u) ? (hi ^ 0x80000000u) : ~hi);

    double se = 0.0, ss = 0.0;
    for (int i = blockIdx.x * blockDim.x + threadIdx.x; i < N;
         i += gridDim.x * blockDim.x) {
        float s = d_scores[i];
        float e = expf(s - gmax);
        se += (double)e;
        ss += (double)e * (double)s;
    }
    __shared__ double shE[RED_THREADS];
    __shared__ double shS[RED_THREADS];
    int t = threadIdx.x;
    shE[t] = se; shS[t] = ss;
    __syncthreads();
    for (int o = RED_THREADS / 2; o > 0; o >>= 1) {
        if (t < o) { shE[t] += shE[t + o]; shS[t] += shS[t + o]; }
        __syncthreads();
    }
    if (t == 0) { d_psumE[blockIdx.x] = shE[0]; d_psumS[blockIdx.x] = shS[0]; }
}

// ---------------- final: combine, write 4 outputs ----------------
__global__ void k_final(float* __restrict__ out) {
    __shared__ double shE[RED_BLOCKS];
    __shared__ double shS[RED_BLOCKS];
    int t = threadIdx.x;
    shE[t] = d_psumE[t];
    shS[t] = d_psumS[t];
    __syncthreads();
    for (int o = RED_BLOCKS / 2; o > 0; o >>= 1) {
        if (t < o) { shE[t] += shE[t + o]; shS[t] += shS[t + o]; }
        __syncthreads();
    }
    if (t == 0) {
        unsigned long long key = d_maxkey;
        unsigned int hi = (unsigned int)(key >> 32);
        float gmax = __uint_as_float((hi & 0x80000000u) ? (hi ^ 0x80000000u) : ~hi);
        unsigned int idx = ~(unsigned int)(key & 0xffffffffu);
        double sumexp = shE[0];
        double sums = shS[0];
        double lg = log(sumexp);
        out[0] = (float)idx;                                  // argmax
        out[1] = (float)(1.0 / sumexp);                       // probs[idx]
        out[2] = (float)(-lg);                                // logp[idx]
        out[3] = (float)((double)gmax + lg - sums / sumexp);  // entropy
    }
}

extern "C" void kernel_launch(void* const* d_in, const int* in_sizes, int n_in,
                              void* d_out, int out_size) {
    const float* x_graph = (const float*)d_in[0];
    const float* x_m     = (const float*)d_in[1];
    const float* x_job   = (const float*)d_in[2];
    const int*   m_ids   = (const int*)d_in[3];
    const int*   job_idx = (const int*)d_in[4];
    const float* W0      = (const float*)d_in[5];
    const float* b0      = (const float*)d_in[6];
    const float* W1      = (const float*)d_in[7];
    const float* b1      = (const float*)d_in[8];
    const float* W2      = (const float*)d_in[9];
    float* out = (float*)d_out;

    int M = in_sizes[1] / H;
    int J = in_sizes[2] / H;
    int N = in_sizes[3];
    if (M > MAXM) M = MAXM;
    if (J > MAXJ) J = MAXJ;
    if (N > MAXN) N = MAXN;

    k_pre_g<<<1, H>>>(x_graph, W0, b0);

    int blocksA = (M + 7) / 8;
    int blocksB = (J + 7) / 8;
    k_pre_rows<<<blocksA + blocksB, H>>>(x_m, x_job, W0, M, J);

    const int smem_main =
        (H * H + 3 * H + (MAIN_THREADS / 32) * NB * H) * (int)sizeof(float);
    cudaFuncSetAttribute(k_main, cudaFuncAttributeMaxDynamicSharedMemorySize,
                         smem_main);
    k_main<<<MAIN_BLOCKS, MAIN_THREADS, smem_main>>>(m_ids, job_idx, W1, b1, W2, N);

    k_sums<<<RED_BLOCKS, RED_THREADS>>>(N);
    k_final<<<1, RED_BLOCKS>>>(out);
}

// round 2
// speedup vs baseline: 1.8283x; 1.8283x over previous
#include <cuda_runtime.h>
#include <math.h>

#define H 128
#define MAXM 2048
#define MAXJ 8192
#define MAXN 262144
#define RED_BLOCKS 512
#define RED_THREADS 256
#define MAIN_BLOCKS 148
#define MAIN_THREADS 256
#define TILE 256       // ops per block-iteration
#define WROWS 32       // rows per warp
#define SA 132         // h0 smem row stride (floats)  -> conflict-free A-frag LDS
#define SB 136         // W1 smem row stride (floats)  -> conflict-free B-frag LDS

// -------- device scratch --------
__device__ float d_g[H];
__device__ float d_A[MAXM * H];
__device__ float d_B[MAXJ * H];
__device__ float d_scores[MAXN];
__device__ unsigned long long d_maxkey;
__device__ double d_psumE[RED_BLOCKS];
__device__ double d_psumS[RED_BLOCKS];

__device__ __forceinline__ unsigned int fkey(float f) {
    unsigned int b = __float_as_uint(f);
    return (b & 0x80000000u) ? ~b : (b | 0x80000000u);
}

__device__ __forceinline__ unsigned int f2tf32(float f) {
    unsigned int r;
    asm("cvt.rna.tf32.f32 %0, %1;" : "=r"(r) : "f"(f));
    return r;
}

__device__ __forceinline__ void mma_tf32(float c[4], const unsigned a[4],
                                         unsigned b0, unsigned b1) {
    asm volatile(
        "mma.sync.aligned.m16n8k8.row.col.f32.tf32.tf32.f32 "
        "{%0,%1,%2,%3}, {%4,%5,%6,%7}, {%8,%9}, {%0,%1,%2,%3};"
        : "+f"(c[0]), "+f"(c[1]), "+f"(c[2]), "+f"(c[3])
        : "r"(a[0]), "r"(a[1]), "r"(a[2]), "r"(a[3]), "r"(b0), "r"(b1));
}

// ---------------- precompute: g, A = x_m@W0[2H:3H], B = x_job@W0[3H:4H] ----------------
__global__ void k_pre(const float* __restrict__ xg,
                      const float* __restrict__ xm,
                      const float* __restrict__ xj,
                      const float* __restrict__ W0,
                      const float* __restrict__ b0,
                      int M, int J) {
    const int t = threadIdx.x;
    if ((int)blockIdx.x == (int)gridDim.x - 1) {
        // g = x_graph @ W0[0:2H] + b0
        __shared__ float s[2 * H];
        if (t == 0) d_maxkey = 0ull;   // reset reduction state every replay
        s[t] = xg[t];
        s[t + H] = xg[t + H];
        __syncthreads();
        float acc = b0[t];
#pragma unroll 8
        for (int k = 0; k < 2 * H; k++) acc += s[k] * W0[k * H + t];
        d_g[t] = acc;
        return;
    }
    const int blocksA = (M + 7) / 8;
    __shared__ float s[8][H];
    const float* src; float* dst;
    int row0, nrows, off;
    if ((int)blockIdx.x < blocksA) {
        row0 = blockIdx.x * 8; nrows = min(8, M - row0);
        src = xm; off = 2 * H; dst = d_A;
    } else {
        row0 = ((int)blockIdx.x - blocksA) * 8; nrows = min(8, J - row0);
        src = xj; off = 3 * H; dst = d_B;
    }
#pragma unroll
    for (int r = 0; r < 8; r++)
        s[r][t] = (r < nrows) ? src[(row0 + r) * H + t] : 0.f;
    __syncthreads();
    float acc[8];
#pragma unroll
    for (int r = 0; r < 8; r++) acc[r] = 0.f;
    const float* Wp = W0 + off * H + t;
#pragma unroll 4
    for (int k = 0; k < H; k++) {
        float w = Wp[k * H];
#pragma unroll
        for (int r = 0; r < 8; r++) acc[r] += s[r][k] * w;
    }
    for (int r = 0; r < nrows; r++) dst[(row0 + r) * H + t] = acc[r];
}

// ---------------- main: gather + tf32 tensor-core layer1 + fused layer2 ----------------
__global__ void __launch_bounds__(MAIN_THREADS, 1)
k_main(const int* __restrict__ m_ids, const int* __restrict__ job_idx,
       const float* __restrict__ W1, const float* __restrict__ b1,
       const float* __restrict__ W2, int N) {
    extern __shared__ float smem[];
    float* W1s = smem;                 // H * SB (tf32 bits)
    float* h0s = W1s + H * SB;         // TILE * SA (tf32 bits)
    float* b1s = h0s + TILE * SA;      // H
    float* w2s = b1s + H;              // H
    __shared__ unsigned long long wkey[MAIN_THREADS / 32];

    const int t = threadIdx.x;
    const int lane = t & 31;
    const int w = t >> 5;
    const int q = lane & 3;        // thread-in-group
    const int g = lane >> 2;       // group id

    // load W1 (convert to tf32), b1, w2
    for (int i = t; i < H * H; i += MAIN_THREADS) {
        int k = i >> 7, n = i & (H - 1);
        W1s[k * SB + n] = __uint_as_float(f2tf32(W1[i]));
    }
    if (t < H) { b1s[t] = b1[t]; w2s[t] = W2[t]; }
    __syncthreads();

    const float4 g4 = *(const float4*)(d_g + 4 * lane);
    unsigned long long wmax = 0ull;

    const int T = (N + TILE - 1) / TILE;
    float* myh = h0s + (w * WROWS) * SA;

    for (int tile = blockIdx.x; tile < T; tile += gridDim.x) {
        const int base = tile * TILE;
        const int wbase = base + w * WROWS;

        // ---- stage h0 = relu(g + A[m] + B[j]) as tf32, warp-local rows ----
#pragma unroll 4
        for (int r = 0; r < WROWS; r++) {
            int id = wbase + r;
            float4 h = make_float4(0.f, 0.f, 0.f, 0.f);
            if (id < N) {
                int m = __ldg(m_ids + id);
                int j = __ldg(job_idx + id);
                float4 a = *(const float4*)(d_A + m * H + 4 * lane);
                float4 b = *(const float4*)(d_B + j * H + 4 * lane);
                h.x = fmaxf(g4.x + a.x + b.x, 0.f);
                h.y = fmaxf(g4.y + a.y + b.y, 0.f);
                h.z = fmaxf(g4.z + a.z + b.z, 0.f);
                h.w = fmaxf(g4.w + a.w + b.w, 0.f);
            }
            uint4 u = make_uint4(f2tf32(h.x), f2tf32(h.y), f2tf32(h.z), f2tf32(h.w));
            *(uint4*)(myh + r * SA + 4 * lane) = u;
        }
        __syncwarp();

        // ---- layer1: two m16 row tiles x 16 n-tiles, K=128 in steps of 8 ----
        float c[2][16][4];
#pragma unroll
        for (int rt = 0; rt < 2; rt++)
#pragma unroll
            for (int nt = 0; nt < 16; nt++)
#pragma unroll
                for (int i = 0; i < 4; i++) c[rt][nt][i] = 0.f;

        for (int k0 = 0; k0 < H; k0 += 8) {
            unsigned af[2][4];
#pragma unroll
            for (int rt = 0; rt < 2; rt++) {
                const float* ap = myh + (16 * rt + g) * SA + k0 + q;
                af[rt][0] = __float_as_uint(ap[0]);
                af[rt][1] = __float_as_uint(ap[8 * SA]);
                af[rt][2] = __float_as_uint(ap[4]);
                af[rt][3] = __float_as_uint(ap[8 * SA + 4]);
            }
            const float* bp = W1s + (k0 + q) * SB + g;
#pragma unroll
            for (int nt = 0; nt < 16; nt++) {
                unsigned b0v = __float_as_uint(bp[nt * 8]);
                unsigned b1v = __float_as_uint(bp[4 * SB + nt * 8]);
                mma_tf32(c[0][nt], af[0], b0v, b1v);
                mma_tf32(c[1][nt], af[1], b0v, b1v);
            }
        }

        // ---- fused layer2: relu(c + b1) . w2 -> per-row score ----
#pragma unroll
        for (int rt = 0; rt < 2; rt++) {
            float p0 = 0.f, p1 = 0.f;
#pragma unroll
            for (int nt = 0; nt < 16; nt++) {
                int n0 = nt * 8 + 2 * q;
                float bb0 = b1s[n0], bb1 = b1s[n0 + 1];
                float ww0 = w2s[n0], ww1 = w2s[n0 + 1];
                p0 += fmaxf(c[rt][nt][0] + bb0, 0.f) * ww0
                    + fmaxf(c[rt][nt][1] + bb1, 0.f) * ww1;
                p1 += fmaxf(c[rt][nt][2] + bb0, 0.f) * ww0
                    + fmaxf(c[rt][nt][3] + bb1, 0.f) * ww1;
            }
            // reduce over the 4-thread quad (lane bits 0..1)
            p0 += __shfl_xor_sync(0xffffffffu, p0, 1);
            p0 += __shfl_xor_sync(0xffffffffu, p0, 2);
            p1 += __shfl_xor_sync(0xffffffffu, p1, 1);
            p1 += __shfl_xor_sync(0xffffffffu, p1, 2);
            if (q == 0) {
                int r0 = wbase + 16 * rt + g;
                if (r0 < N) {
                    d_scores[r0] = p0;
                    unsigned long long key =
                        ((unsigned long long)fkey(p0) << 32) |
                        (unsigned long long)(~(unsigned int)r0);
                    if (key > wmax) wmax = key;
                }
                int r1 = r0 + 8;
                if (r1 < N) {
                    d_scores[r1] = p1;
                    unsigned long long key =
                        ((unsigned long long)fkey(p1) << 32) |
                        (unsigned long long)(~(unsigned int)r1);
                    if (key > wmax) wmax = key;
                }
            }
        }
        __syncwarp();   // h0s reuse next tile
    }

    // warp max -> block max -> global
#pragma unroll
    for (int off = 16; off > 0; off >>= 1) {
        unsigned long long o = __shfl_xor_sync(0xffffffffu, wmax, off);
        if (o > wmax) wmax = o;
    }
    if (lane == 0) wkey[w] = wmax;
    __syncthreads();
    if (t == 0) {
        unsigned long long k = wkey[0];
#pragma unroll
        for (int i = 1; i < MAIN_THREADS / 32; i++) k = max(k, wkey[i]);
        atomicMax(&d_maxkey, k);
    }
}

// ---------------- pass 2: partial sums of exp(s - max) and s*exp(s - max) ----------------
__global__ void k_sums(int N) {
    unsigned long long key = d_maxkey;
    unsigned int hi = (unsigned int)(key >> 32);
    float gmax = __uint_as_float((hi & 0x80000000u) ? (hi ^ 0x80000000u) : ~hi);

    double se = 0.0, ss = 0.0;
    for (int i = blockIdx.x * blockDim.x + threadIdx.x; i < N;
         i += gridDim.x * blockDim.x) {
        float s = d_scores[i];
        float e = expf(s - gmax);
        se += (double)e;
        ss += (double)e * (double)s;
    }
    __shared__ double shE[RED_THREADS];
    __shared__ double shS[RED_THREADS];
    int t = threadIdx.x;
    shE[t] = se; shS[t] = ss;
    __syncthreads();
    for (int o = RED_THREADS / 2; o > 0; o >>= 1) {
        if (t < o) { shE[t] += shE[t + o]; shS[t] += shS[t + o]; }
        __syncthreads();
    }
    if (t == 0) { d_psumE[blockIdx.x] = shE[0]; d_psumS[blockIdx.x] = shS[0]; }
}

// ---------------- final: combine, write 4 outputs ----------------
__global__ void k_final(float* __restrict__ out) {
    __shared__ double shE[RED_BLOCKS];
    __shared__ double shS[RED_BLOCKS];
    int t = threadIdx.x;
    shE[t] = d_psumE[t];
    shS[t] = d_psumS[t];
    __syncthreads();
    for (int o = RED_BLOCKS / 2; o > 0; o >>= 1) {
        if (t < o) { shE[t] += shE[t + o]; shS[t] += shS[t + o]; }
        __syncthreads();
    }
    if (t == 0) {
        unsigned long long key = d_maxkey;
        unsigned int hi = (unsigned int)(key >> 32);
        float gmax = __uint_as_float((hi & 0x80000000u) ? (hi ^ 0x80000000u) : ~hi);
        unsigned int idx = ~(unsigned int)(key & 0xffffffffu);
        double sumexp = shE[0];
        double sums = shS[0];
        double lg = log(sumexp);
        out[0] = (float)idx;
        out[1] = (float)(1.0 / sumexp);
        out[2] = (float)(-lg);
        out[3] = (float)((double)gmax + lg - sums / sumexp);
    }
}

extern "C" void kernel_launch(void* const* d_in, const int* in_sizes, int n_in,
                              void* d_out, int out_size) {
    const float* x_graph = (const float*)d_in[0];
    const float* x_m     = (const float*)d_in[1];
    const float* x_job   = (const float*)d_in[2];
    const int*   m_ids   = (const int*)d_in[3];
    const int*   job_idx = (const int*)d_in[4];
    const float* W0      = (const float*)d_in[5];
    const float* b0      = (const float*)d_in[6];
    const float* W1      = (const float*)d_in[7];
    const float* b1      = (const float*)d_in[8];
    const float* W2      = (const float*)d_in[9];
    float* out = (float*)d_out;

    int M = in_sizes[1] / H;
    int J = in_sizes[2] / H;
    int N = in_sizes[3];
    if (M > MAXM) M = MAXM;
    if (J > MAXJ) J = MAXJ;
    if (N > MAXN) N = MAXN;

    int blocksA = (M + 7) / 8;
    int blocksB = (J + 7) / 8;
    k_pre<<<blocksA + blocksB + 1, H>>>(x_graph, x_m, x_job, W0, b0, M, J);

    const int smem_main =
        (H * SB + TILE * SA + 2 * H) * (int)sizeof(float);
    static int smem_set = 0;
    if (!smem_set) {
        cudaFuncSetAttribute(k_main, cudaFuncAttributeMaxDynamicSharedMemorySize,
                             smem_main);
        smem_set = 1;
    }
    k_main<<<MAIN_BLOCKS, MAIN_THREADS, smem_main>>>(m_ids, job_idx, W1, b1, W2, N);

    k_sums<<<RED_BLOCKS, RED_THREADS>>>(N);
    k_final<<<1, RED_BLOCKS>>>(out);
}

// round 3
// speedup vs baseline: 1.8894x; 1.0334x over previous
#include <cuda_runtime.h>
#include <math.h>

#define H 128
#define MAXM 2048
#define MAXJ 8192
#define MAIN_BLOCKS 148
#define MAIN_THREADS 256
#define TILE 256       // ops per block-iteration
#define WROWS 32       // rows per warp
#define SA 132         // h0 smem row stride (floats)
#define PREROWS 16

// -------- device scratch --------
__device__ float d_g[H];
__device__ float d_A[MAXM * H];
__device__ float d_B[MAXJ * H];
__device__ unsigned long long d_maxkey;
__device__ float d_blkM[MAIN_BLOCKS];
__device__ float d_blkE[MAIN_BLOCKS];
__device__ float d_blkS[MAIN_BLOCKS];

__device__ __forceinline__ unsigned int fkey(float f) {
    unsigned int b = __float_as_uint(f);
    return (b & 0x80000000u) ? ~b : (b | 0x80000000u);
}

__device__ __forceinline__ unsigned int f2tf32(float f) {
    unsigned int r;
    asm("cvt.rna.tf32.f32 %0, %1;" : "=r"(r) : "f"(f));
    return r;
}

__device__ __forceinline__ void mma_tf32(float c[4], const unsigned a[4],
                                         unsigned b0, unsigned b1) {
    asm volatile(
        "mma.sync.aligned.m16n8k8.row.col.f32.tf32.tf32.f32 "
        "{%0,%1,%2,%3}, {%4,%5,%6,%7}, {%8,%9}, {%0,%1,%2,%3};"
        : "+f"(c[0]), "+f"(c[1]), "+f"(c[2]), "+f"(c[3])
        : "r"(a[0]), "r"(a[1]), "r"(a[2]), "r"(a[3]), "r"(b0), "r"(b1));
}

// online-softmax triple merge
__device__ __forceinline__ void osm_merge(float& m, float& se, float& ss,
                                          float m2, float se2, float ss2) {
    float M = fmaxf(m, se2 > 0.f ? m2 : m);
    if (m2 > M) M = m2;
    float a1 = (se > 0.f) ? expf(m - M) : 0.f;
    float a2 = (se2 > 0.f) ? expf(m2 - M) : 0.f;
    se = se * a1 + se2 * a2;
    ss = ss * a1 + ss2 * a2;
    m = M;
}

// ---------------- precompute: g, A = x_m@W0[2H:3H], B = x_job@W0[3H:4H] ----------------
__global__ void k_pre(const float* __restrict__ xg,
                      const float* __restrict__ xm,
                      const float* __restrict__ xj,
                      const float* __restrict__ W0,
                      const float* __restrict__ b0,
                      int M, int J) {
    const int t = threadIdx.x;
    if ((int)blockIdx.x == (int)gridDim.x - 1) {
        __shared__ float s[2 * H];
        if (t == 0) d_maxkey = 0ull;
        s[t] = xg[t];
        s[t + H] = xg[t + H];
        __syncthreads();
        float acc = b0[t];
#pragma unroll 8
        for (int k = 0; k < 2 * H; k++) acc += s[k] * W0[k * H + t];
        d_g[t] = acc;
        return;
    }
    const int blocksA = (M + PREROWS - 1) / PREROWS;
    __shared__ float s[PREROWS][H];
    const float* src; float* dst;
    int row0, nrows, off;
    if ((int)blockIdx.x < blocksA) {
        row0 = blockIdx.x * PREROWS; nrows = min(PREROWS, M - row0);
        src = xm; off = 2 * H; dst = d_A;
    } else {
        row0 = ((int)blockIdx.x - blocksA) * PREROWS; nrows = min(PREROWS, J - row0);
        src = xj; off = 3 * H; dst = d_B;
    }
#pragma unroll
    for (int r = 0; r < PREROWS; r++)
        s[r][t] = (r < nrows) ? src[(row0 + r) * H + t] : 0.f;
    __syncthreads();
    float acc[PREROWS];
#pragma unroll
    for (int r = 0; r < PREROWS; r++) acc[r] = 0.f;
    const float* Wp = W0 + off * H + t;
#pragma unroll 2
    for (int k = 0; k < H; k++) {
        float w = Wp[k * H];
#pragma unroll
        for (int r = 0; r < PREROWS; r++) acc[r] += s[r][k] * w;
    }
    for (int r = 0; r < nrows; r++) dst[(row0 + r) * H + t] = acc[r];
}

// ---------------- main ----------------
// smem: W1pk[16][32][36] tf32-packed, h0s[TILE][SA], b1w2[16][4] float4
__global__ void __launch_bounds__(MAIN_THREADS, 1)
k_main(const int* __restrict__ m_ids, const int* __restrict__ job_idx,
       const float* __restrict__ W1, const float* __restrict__ b1,
       const float* __restrict__ W2, int N) {
    extern __shared__ float smem[];
    float* W1pk = smem;                        // 16*32*36 = 18432 floats
    float* h0s  = W1pk + 16 * 32 * 36;         // TILE*SA  = 33792 floats
    float4* pk  = (float4*)(h0s + TILE * SA);  // 16*4 float4 = 256 floats
    __shared__ unsigned long long wkey[MAIN_THREADS / 32];
    __shared__ float wM[MAIN_THREADS / 32], wE[MAIN_THREADS / 32], wS[MAIN_THREADS / 32];

    const int t = threadIdx.x;
    const int lane = t & 31;
    const int w = t >> 5;
    const int q = lane & 3;
    const int g = lane >> 2;

    // pack W1 -> W1pk[ks][lane][nt][2]: (W1[8ks+q][8nt+g], W1[8ks+q+4][8nt+g])
    for (int i = t; i < 16 * 32 * 16 * 2; i += MAIN_THREADS) {
        int c  = i & 1;
        int nt = (i >> 1) & 15;
        int ln = (i >> 5) & 31;
        int ks = i >> 10;
        int qq = ln & 3, gg = ln >> 2;
        int krow = 8 * ks + qq + 4 * c;
        int ncol = 8 * nt + gg;
        W1pk[(ks * 32 + ln) * 36 + nt * 2 + c] =
            __uint_as_float(f2tf32(W1[krow * H + ncol]));
    }
    // pack (b1, w2) -> pk[nt][q] = (b1[8nt+2q], b1[8nt+2q+1], w2[8nt+2q], w2[8nt+2q+1])
    if (t < 64) {
        int nt = t >> 2, qq = t & 3;
        int n0 = 8 * nt + 2 * qq;
        pk[nt * 4 + qq] = make_float4(b1[n0], b1[n0 + 1], W2[n0], W2[n0 + 1]);
    }
    __syncthreads();

    const float4 g4 = *(const float4*)(d_g + 4 * lane);
    unsigned long long wmax = 0ull;
    float om = -INFINITY, ose = 0.f, oss = 0.f;

    const int T = (N + TILE - 1) / TILE;
    float* myh = h0s + (w * WROWS) * SA;

    for (int tile = blockIdx.x; tile < T; tile += gridDim.x) {
        const int wbase = tile * TILE + w * WROWS;

        // ---- coalesced id preload ----
        int idrow = wbase + lane;
        int my_m = (idrow < N) ? m_ids[idrow] : 0;
        int my_j = (idrow < N) ? job_idx[idrow] : 0;

        // ---- stage h0 = relu(g + A[m] + B[j]) as tf32 ----
#pragma unroll 8
        for (int r = 0; r < WROWS; r++) {
            int m = __shfl_sync(0xffffffffu, my_m, r);
            int j = __shfl_sync(0xffffffffu, my_j, r);
            float4 h = make_float4(0.f, 0.f, 0.f, 0.f);
            if (wbase + r < N) {
                float4 a = *(const float4*)(d_A + m * H + 4 * lane);
                float4 b = *(const float4*)(d_B + j * H + 4 * lane);
                h.x = fmaxf(g4.x + a.x + b.x, 0.f);
                h.y = fmaxf(g4.y + a.y + b.y, 0.f);
                h.z = fmaxf(g4.z + a.z + b.z, 0.f);
                h.w = fmaxf(g4.w + a.w + b.w, 0.f);
            }
            uint4 u = make_uint4(f2tf32(h.x), f2tf32(h.y), f2tf32(h.z), f2tf32(h.w));
            *(uint4*)(myh + r * SA + 4 * lane) = u;
        }
        __syncwarp();

        // ---- layer1 tf32 MMA: 2 row-tiles x 16 n-tiles, K=128 ----
        float c[2][16][4];
#pragma unroll
        for (int rt = 0; rt < 2; rt++)
#pragma unroll
            for (int nt = 0; nt < 16; nt++)
#pragma unroll
                for (int i = 0; i < 4; i++) c[rt][nt][i] = 0.f;

        for (int ks = 0; ks < 16; ks++) {
            const int k0 = ks * 8;
            unsigned af[2][4];
#pragma unroll
            for (int rt = 0; rt < 2; rt++) {
                const float* ap = myh + (16 * rt + g) * SA + k0 + q;
                af[rt][0] = __float_as_uint(ap[0]);
                af[rt][1] = __float_as_uint(ap[8 * SA]);
                af[rt][2] = __float_as_uint(ap[4]);
                af[rt][3] = __float_as_uint(ap[8 * SA + 4]);
            }
            const float4* bp = (const float4*)(W1pk + (ks * 32 + lane) * 36);
#pragma unroll
            for (int np = 0; np < 8; np++) {
                float4 bv = bp[np];   // (b0[2np], b1[2np], b0[2np+1], b1[2np+1])
                unsigned b00 = __float_as_uint(bv.x), b01 = __float_as_uint(bv.y);
                unsigned b10 = __float_as_uint(bv.z), b11 = __float_as_uint(bv.w);
                mma_tf32(c[0][2 * np],     af[0], b00, b01);
                mma_tf32(c[1][2 * np],     af[1], b00, b01);
                mma_tf32(c[0][2 * np + 1], af[0], b10, b11);
                mma_tf32(c[1][2 * np + 1], af[1], b10, b11);
            }
        }

        // ---- fused layer2 + online softmax ----
#pragma unroll
        for (int rt = 0; rt < 2; rt++) {
            float p0 = 0.f, p1 = 0.f;
#pragma unroll
            for (int nt = 0; nt < 16; nt++) {
                float4 v = pk[nt * 4 + q];
                p0 += fmaxf(c[rt][nt][0] + v.x, 0.f) * v.z
                    + fmaxf(c[rt][nt][1] + v.y, 0.f) * v.w;
                p1 += fmaxf(c[rt][nt][2] + v.x, 0.f) * v.z
                    + fmaxf(c[rt][nt][3] + v.y, 0.f) * v.w;
            }
            p0 += __shfl_xor_sync(0xffffffffu, p0, 1);
            p0 += __shfl_xor_sync(0xffffffffu, p0, 2);
            p1 += __shfl_xor_sync(0xffffffffu, p1, 1);
            p1 += __shfl_xor_sync(0xffffffffu, p1, 2);
            if (q == 0) {
                int r0 = wbase + 16 * rt + g;
                if (r0 < N) {
                    unsigned long long key =
                        ((unsigned long long)fkey(p0) << 32) |
                        (unsigned long long)(~(unsigned int)r0);
                    if (key > wmax) wmax = key;
                    if (p0 > om) {
                        float cc = expf(om - p0);
                        ose = ose * cc + 1.f;
                        oss = oss * cc + p0;
                        om = p0;
                    } else {
                        float e = expf(p0 - om);
                        ose += e;
                        oss += p0 * e;
                    }
                }
                int r1 = r0 + 8;
                if (r1 < N) {
                    unsigned long long key =
                        ((unsigned long long)fkey(p1) << 32) |
                        (unsigned long long)(~(unsigned int)r1);
                    if (key > wmax) wmax = key;
                    if (p1 > om) {
                        float cc = expf(om - p1);
                        ose = ose * cc + 1.f;
                        oss = oss * cc + p1;
                        om = p1;
                    } else {
                        float e = expf(p1 - om);
                        ose += e;
                        oss += p1 * e;
                    }
                }
            }
        }
        __syncwarp();
    }

    // ---- warp reduce (max key + online triple) ----
#pragma unroll
    for (int off = 16; off > 0; off >>= 1) {
        unsigned long long o = __shfl_xor_sync(0xffffffffu, wmax, off);
        if (o > wmax) wmax = o;
        float m2  = __shfl_xor_sync(0xffffffffu, om, off);
        float se2 = __shfl_xor_sync(0xffffffffu, ose, off);
        float ss2 = __shfl_xor_sync(0xffffffffu, oss, off);
        osm_merge(om, ose, oss, m2, se2, ss2);
    }
    if (lane == 0) { wkey[w] = wmax; wM[w] = om; wE[w] = ose; wS[w] = oss; }
    __syncthreads();
    if (t == 0) {
        unsigned long long k = wkey[0];
        float M = wM[0], E = wE[0], S = wS[0];
#pragma unroll
        for (int i = 1; i < MAIN_THREADS / 32; i++) {
            if (wkey[i] > k) k = wkey[i];
            osm_merge(M, E, S, wM[i], wE[i], wS[i]);
        }
        atomicMax(&d_maxkey, k);
        d_blkM[blockIdx.x] = M;
        d_blkE[blockIdx.x] = E;
        d_blkS[blockIdx.x] = S;
    }
}

// ---------------- final: merge 148 block triples, write 4 outputs ----------------
__global__ void k_final(float* __restrict__ out, int nblk) {
    __shared__ double shE[256], shS[256];
    __shared__ float shM[256];
    int t = threadIdx.x;
    float M = -INFINITY, E = 0.f, S = 0.f;
    if (t < nblk) { M = d_blkM[t]; E = d_blkE[t]; S = d_blkS[t]; }
    shM[t] = M; shE[t] = E; shS[t] = S;
    __syncthreads();
    for (int o = 128; o > 0; o >>= 1) {
        if (t < o) {
            float m1 = shM[t], m2 = shM[t + o];
            double e1 = shE[t], e2 = shE[t + o];
            double s1 = shS[t], s2 = shS[t + o];
            float Mx = fmaxf(m1, m2);
            double a1 = (e1 > 0.0) ? exp((double)(m1 - Mx)) : 0.0;
            double a2 = (e2 > 0.0) ? exp((double)(m2 - Mx)) : 0.0;
            shM[t] = Mx;
            shE[t] = e1 * a1 + e2 * a2;
            shS[t] = s1 * a1 + s2 * a2;
        }
        __syncthreads();
    }
    if (t == 0) {
        unsigned long long key = d_maxkey;
        unsigned int idx = ~(unsigned int)(key & 0xffffffffu);
        double sumexp = shE[0];
        double sums = shS[0];
        double lg = log(sumexp);
        out[0] = (float)idx;
        out[1] = (float)(1.0 / sumexp);
        out[2] = (float)(-lg);
        out[3] = (float)((double)shM[0] + lg - sums / sumexp);
    }
}

extern "C" void kernel_launch(void* const* d_in, const int* in_sizes, int n_in,
                              void* d_out, int out_size) {
    const float* x_graph = (const float*)d_in[0];
    const float* x_m     = (const float*)d_in[1];
    const float* x_job   = (const float*)d_in[2];
    const int*   m_ids   = (const int*)d_in[3];
    const int*   job_idx = (const int*)d_in[4];
    const float* W0      = (const float*)d_in[5];
    const float* b0      = (const float*)d_in[6];
    const float* W1      = (const float*)d_in[7];
    const float* b1      = (const float*)d_in[8];
    const float* W2      = (const float*)d_in[9];
    float* out = (float*)d_out;

    int M = in_sizes[1] / H;
    int J = in_sizes[2] / H;
    int N = in_sizes[3];
    if (M > MAXM) M = MAXM;
    if (J > MAXJ) J = MAXJ;

    int blocksA = (M + PREROWS - 1) / PREROWS;
    int blocksB = (J + PREROWS - 1) / PREROWS;
    k_pre<<<blocksA + blocksB + 1, H>>>(x_graph, x_m, x_job, W0, b0, M, J);

    const int smem_main =
        (16 * 32 * 36 + TILE * SA + 16 * 4 * 4) * (int)sizeof(float);
    static int smem_set = 0;
    if (!smem_set) {
        cudaFuncSetAttribute(k_main, cudaFuncAttributeMaxDynamicSharedMemorySize,
                             smem_main);
        smem_set = 1;
    }
    k_main<<<MAIN_BLOCKS, MAIN_THREADS, smem_main>>>(m_ids, job_idx, W1, b1, W2, N);

    k_final<<<1, 256>>>(out, MAIN_BLOCKS);
}

// round 4
// speedup vs baseline: 2.2615x; 1.1969x over previous
#include <cuda_runtime.h>
#include <cuda_bf16.h>
#include <math.h>

#define H 128
#define MAXM 2048
#define MAXJ 8192
#define MAIN_BLOCKS 148
#define MAIN_THREADS 256
#define TILE 256       // ops per block-iteration
#define WROWS 32       // rows per warp
#define SAW 68         // h0 smem row stride in 32-bit words (64 data + 4 pad)
#define PREROWS 16

// -------- device scratch --------
__device__ float d_g[H];
__device__ float d_A[MAXM * H];
__device__ float d_B[MAXJ * H];
__device__ unsigned long long d_maxkey;
__device__ unsigned int d_ticket;
__device__ float d_blkM[MAIN_BLOCKS];
__device__ float d_blkE[MAIN_BLOCKS];
__device__ float d_blkS[MAIN_BLOCKS];

__device__ __forceinline__ unsigned int fkey(float f) {
    unsigned int b = __float_as_uint(f);
    return (b & 0x80000000u) ? ~b : (b | 0x80000000u);
}

__device__ __forceinline__ unsigned int bf2(float lo, float hi) {
    __nv_bfloat162 v = __float22bfloat162_rn(make_float2(lo, hi));
    return *(unsigned int*)&v;
}

__device__ __forceinline__ void mma_bf16(float c[4], const unsigned a[4],
                                         unsigned b0, unsigned b1) {
    asm volatile(
        "mma.sync.aligned.m16n8k16.row.col.f32.bf16.bf16.f32 "
        "{%0,%1,%2,%3}, {%4,%5,%6,%7}, {%8,%9}, {%0,%1,%2,%3};"
        : "+f"(c[0]), "+f"(c[1]), "+f"(c[2]), "+f"(c[3])
        : "r"(a[0]), "r"(a[1]), "r"(a[2]), "r"(a[3]), "r"(b0), "r"(b1));
}

// online-softmax triple merge
__device__ __forceinline__ void osm_merge(float& m, float& se, float& ss,
                                          float m2, float se2, float ss2) {
    float M = fmaxf(m, se2 > 0.f ? m2 : m);
    if (m2 > M) M = m2;
    float a1 = (se > 0.f) ? expf(m - M) : 0.f;
    float a2 = (se2 > 0.f) ? expf(m2 - M) : 0.f;
    se = se * a1 + se2 * a2;
    ss = ss * a1 + ss2 * a2;
    m = M;
}

// ---------------- precompute: g, A = x_m@W0[2H:3H], B = x_job@W0[3H:4H] ----------------
__global__ void k_pre(const float* __restrict__ xg,
                      const float* __restrict__ xm,
                      const float* __restrict__ xj,
                      const float* __restrict__ W0,
                      const float* __restrict__ b0,
                      int M, int J) {
    const int t = threadIdx.x;
    if ((int)blockIdx.x == (int)gridDim.x - 1) {
        __shared__ float s[2 * H];
        if (t == 0) { d_maxkey = 0ull; d_ticket = 0u; }
        s[t] = xg[t];
        s[t + H] = xg[t + H];
        __syncthreads();
        float acc = b0[t];
        for (int k0 = 0; k0 < 2 * H; k0 += 8) {
            float wv[8];
#pragma unroll
            for (int u = 0; u < 8; u++) wv[u] = W0[(k0 + u) * H + t];
#pragma unroll
            for (int u = 0; u < 8; u++) acc += s[k0 + u] * wv[u];
        }
        d_g[t] = acc;
        return;
    }
    const int blocksA = (M + PREROWS - 1) / PREROWS;
    __shared__ float s[PREROWS][H];
    const float* src; float* dst;
    int row0, nrows, off;
    if ((int)blockIdx.x < blocksA) {
        row0 = blockIdx.x * PREROWS; nrows = min(PREROWS, M - row0);
        src = xm; off = 2 * H; dst = d_A;
    } else {
        row0 = ((int)blockIdx.x - blocksA) * PREROWS; nrows = min(PREROWS, J - row0);
        src = xj; off = 3 * H; dst = d_B;
    }
#pragma unroll
    for (int r = 0; r < PREROWS; r++)
        s[r][t] = (r < nrows) ? src[(row0 + r) * H + t] : 0.f;
    __syncthreads();
    float acc[PREROWS];
#pragma unroll
    for (int r = 0; r < PREROWS; r++) acc[r] = 0.f;
    const float* Wp = W0 + off * H + t;
#pragma unroll 1
    for (int k0 = 0; k0 < H; k0 += 8) {
        float wv[8];
#pragma unroll
        for (int u = 0; u < 8; u++) wv[u] = Wp[(k0 + u) * H];
#pragma unroll
        for (int u = 0; u < 8; u++) {
#pragma unroll
            for (int r = 0; r < PREROWS; r++) acc[r] += s[r][k0 + u] * wv[u];
        }
    }
    for (int r = 0; r < nrows; r++) dst[(row0 + r) * H + t] = acc[r];
}

// ---------------- main: gather + bf16 MMA layer1 + fused layer2 + softmax ----------------
// dyn smem: W1pk[8][32][36] uints (bf16x2), h0s[TILE][SAW] uints, pk[16][4] float4
__global__ void __launch_bounds__(MAIN_THREADS, 1)
k_main(const int* __restrict__ m_ids, const int* __restrict__ job_idx,
       const float* __restrict__ W1, const float* __restrict__ b1,
       const float* __restrict__ W2, int N, float* __restrict__ out) {
    extern __shared__ unsigned int smem[];
    unsigned int* W1pk = smem;                      // 8*32*36 = 9216 words
    unsigned int* h0s  = W1pk + 8 * 32 * 36;        // TILE*SAW = 17408 words
    float4* pk = (float4*)(h0s + TILE * SAW);       // 16*4 float4
    __shared__ unsigned long long wkey[MAIN_THREADS / 32];
    __shared__ float wM[MAIN_THREADS / 32], wE[MAIN_THREADS / 32], wS[MAIN_THREADS / 32];
    __shared__ int isLast;
    __shared__ double fE[MAIN_THREADS], fS[MAIN_THREADS];
    __shared__ float fM[MAIN_THREADS];

    const int t = threadIdx.x;
    const int lane = t & 31;
    const int w = t >> 5;
    const int q = lane & 3;
    const int g = lane >> 2;

    // pack W1 -> bf16x2 fragments: W1pk[ks][ln][nt*2+c] =
    //   {W1[16ks+2q+8c][8nt+g], W1[16ks+2q+8c+1][8nt+g]}
    for (int i = t; i < 8 * 32 * 16 * 2; i += MAIN_THREADS) {
        int c  = i & 1;
        int nt = (i >> 1) & 15;
        int ln = (i >> 5) & 31;
        int ks = (i >> 10) & 7;
        int qq = ln & 3, gg = ln >> 2;
        int k0 = 16 * ks + 2 * qq + 8 * c;
        int col = 8 * nt + gg;
        W1pk[(ks * 32 + ln) * 36 + nt * 2 + c] =
            bf2(W1[k0 * H + col], W1[(k0 + 1) * H + col]);
    }
    // pack (b1, w2): pk[nt][q] = (b1[8nt+2q], b1[8nt+2q+1], w2[8nt+2q], w2[8nt+2q+1])
    if (t < 64) {
        int nt = t >> 2, qq = t & 3;
        int n0 = 8 * nt + 2 * qq;
        pk[nt * 4 + qq] = make_float4(b1[n0], b1[n0 + 1], W2[n0], W2[n0 + 1]);
    }
    __syncthreads();

    const float4 g4 = *(const float4*)(d_g + 4 * lane);
    unsigned long long wmax = 0ull;
    float om = -INFINITY, ose = 0.f, oss = 0.f;

    const int T = (N + TILE - 1) / TILE;
    unsigned int* myh = h0s + (w * WROWS) * SAW;

    for (int tile = blockIdx.x; tile < T; tile += gridDim.x) {
        const int wbase = tile * TILE + w * WROWS;

        // coalesced id preload
        int idrow = wbase + lane;
        int my_m = (idrow < N) ? m_ids[idrow] : 0;
        int my_j = (idrow < N) ? job_idx[idrow] : 0;

        // stage h0 = relu(g + A[m] + B[j]) as bf16x2
#pragma unroll 8
        for (int r = 0; r < WROWS; r++) {
            int m = __shfl_sync(0xffffffffu, my_m, r);
            int j = __shfl_sync(0xffffffffu, my_j, r);
            float4 h = make_float4(0.f, 0.f, 0.f, 0.f);
            if (wbase + r < N) {
                float4 a = *(const float4*)(d_A + m * H + 4 * lane);
                float4 b = *(const float4*)(d_B + j * H + 4 * lane);
                h.x = fmaxf(g4.x + a.x + b.x, 0.f);
                h.y = fmaxf(g4.y + a.y + b.y, 0.f);
                h.z = fmaxf(g4.z + a.z + b.z, 0.f);
                h.w = fmaxf(g4.w + a.w + b.w, 0.f);
            }
            uint2 u = make_uint2(bf2(h.x, h.y), bf2(h.z, h.w));
            *(uint2*)(myh + r * SAW + 2 * lane) = u;
        }
        __syncwarp();

        // layer1 bf16 MMA: 2 row-tiles x 16 n-tiles, K=128 in 8 k16-steps
        float c[2][16][4];
#pragma unroll
        for (int rt = 0; rt < 2; rt++)
#pragma unroll
            for (int nt = 0; nt < 16; nt++)
#pragma unroll
                for (int i = 0; i < 4; i++) c[rt][nt][i] = 0.f;

#pragma unroll
        for (int ks = 0; ks < 8; ks++) {
            unsigned af[2][4];
#pragma unroll
            for (int rt = 0; rt < 2; rt++) {
                const unsigned int* ap = myh + (16 * rt + g) * SAW + 8 * ks + q;
                af[rt][0] = ap[0];
                af[rt][1] = ap[8 * SAW];
                af[rt][2] = ap[4];
                af[rt][3] = ap[8 * SAW + 4];
            }
            const uint4* bp = (const uint4*)(W1pk + (ks * 32 + lane) * 36);
#pragma unroll
            for (int np = 0; np < 8; np++) {
                uint4 bv = bp[np];
                mma_bf16(c[0][2 * np],     af[0], bv.x, bv.y);
                mma_bf16(c[1][2 * np],     af[1], bv.x, bv.y);
                mma_bf16(c[0][2 * np + 1], af[0], bv.z, bv.w);
                mma_bf16(c[1][2 * np + 1], af[1], bv.z, bv.w);
            }
        }

        // fused layer2 + online softmax
#pragma unroll
        for (int rt = 0; rt < 2; rt++) {
            float p0 = 0.f, p1 = 0.f;
#pragma unroll
            for (int nt = 0; nt < 16; nt++) {
                float4 v = pk[nt * 4 + q];
                p0 += fmaxf(c[rt][nt][0] + v.x, 0.f) * v.z
                    + fmaxf(c[rt][nt][1] + v.y, 0.f) * v.w;
                p1 += fmaxf(c[rt][nt][2] + v.x, 0.f) * v.z
                    + fmaxf(c[rt][nt][3] + v.y, 0.f) * v.w;
            }
            p0 += __shfl_xor_sync(0xffffffffu, p0, 1);
            p0 += __shfl_xor_sync(0xffffffffu, p0, 2);
            p1 += __shfl_xor_sync(0xffffffffu, p1, 1);
            p1 += __shfl_xor_sync(0xffffffffu, p1, 2);
            if (q == 0) {
                int r0 = wbase + 16 * rt + g;
                if (r0 < N) {
                    unsigned long long key =
                        ((unsigned long long)fkey(p0) << 32) |
                        (unsigned long long)(~(unsigned int)r0);
                    if (key > wmax) wmax = key;
                    if (p0 > om) {
                        float cc = expf(om - p0);
                        ose = ose * cc + 1.f;
                        oss = oss * cc + p0;
                        om = p0;
                    } else {
                        float e = expf(p0 - om);
                        ose += e; oss += p0 * e;
                    }
                }
                int r1 = r0 + 8;
                if (r1 < N) {
                    unsigned long long key =
                        ((unsigned long long)fkey(p1) << 32) |
                        (unsigned long long)(~(unsigned int)r1);
                    if (key > wmax) wmax = key;
                    if (p1 > om) {
                        float cc = expf(om - p1);
                        ose = ose * cc + 1.f;
                        oss = oss * cc + p1;
                        om = p1;
                    } else {
                        float e = expf(p1 - om);
                        ose += e; oss += p1 * e;
                    }
                }
            }
        }
        __syncwarp();
    }

    // warp reduce
#pragma unroll
    for (int off = 16; off > 0; off >>= 1) {
        unsigned long long o = __shfl_xor_sync(0xffffffffu, wmax, off);
        if (o > wmax) wmax = o;
        float m2  = __shfl_xor_sync(0xffffffffu, om, off);
        float se2 = __shfl_xor_sync(0xffffffffu, ose, off);
        float ss2 = __shfl_xor_sync(0xffffffffu, oss, off);
        osm_merge(om, ose, oss, m2, se2, ss2);
    }
    if (lane == 0) { wkey[w] = wmax; wM[w] = om; wE[w] = ose; wS[w] = oss; }
    __syncthreads();
    if (t == 0) {
        unsigned long long k = wkey[0];
        float M = wM[0], E = wE[0], S = wS[0];
#pragma unroll
        for (int i = 1; i < MAIN_THREADS / 32; i++) {
            if (wkey[i] > k) k = wkey[i];
            osm_merge(M, E, S, wM[i], wE[i], wS[i]);
        }
        atomicMax(&d_maxkey, k);
        d_blkM[blockIdx.x] = M;
        d_blkE[blockIdx.x] = E;
        d_blkS[blockIdx.x] = S;
        __threadfence();
        unsigned prev = atomicAdd(&d_ticket, 1u);
        isLast = (prev == gridDim.x - 1u);
    }
    __syncthreads();

    // last block merges all block triples and writes the 4 outputs
    if (isLast) {
        float M = -INFINITY; double E = 0.0, S = 0.0;
        if (t < (int)gridDim.x) { M = d_blkM[t]; E = d_blkE[t]; S = d_blkS[t]; }
        fM[t] = M; fE[t] = E; fS[t] = S;
        __syncthreads();
        for (int o = MAIN_THREADS / 2; o > 0; o >>= 1) {
            if (t < o) {
                float m1 = fM[t], m2 = fM[t + o];
                double e1 = fE[t], e2 = fE[t + o];
                double s1 = fS[t], s2 = fS[t + o];
                float Mx = fmaxf(m1, m2);
                double a1 = (e1 > 0.0) ? exp((double)(m1 - Mx)) : 0.0;
                double a2 = (e2 > 0.0) ? exp((double)(m2 - Mx)) : 0.0;
                fM[t] = Mx;
                fE[t] = e1 * a1 + e2 * a2;
                fS[t] = s1 * a1 + s2 * a2;
            }
            __syncthreads();
        }
        if (t == 0) {
            unsigned long long key = d_maxkey;
            unsigned int idx = ~(unsigned int)(key & 0xffffffffu);
            double sumexp = fE[0];
            double sums = fS[0];
            double lg = log(sumexp);
            out[0] = (float)idx;
            out[1] = (float)(1.0 / sumexp);
            out[2] = (float)(-lg);
            out[3] = (float)((double)fM[0] + lg - sums / sumexp);
        }
    }
}

extern "C" void kernel_launch(void* const* d_in, const int* in_sizes, int n_in,
                              void* d_out, int out_size) {
    const float* x_graph = (const float*)d_in[0];
    const float* x_m     = (const float*)d_in[1];
    const float* x_job   = (const float*)d_in[2];
    const int*   m_ids   = (const int*)d_in[3];
    const int*   job_idx = (const int*)d_in[4];
    const float* W0      = (const float*)d_in[5];
    const float* b0      = (const float*)d_in[6];
    const float* W1      = (const float*)d_in[7];
    const float* b1      = (const float*)d_in[8];
    const float* W2      = (const float*)d_in[9];
    float* out = (float*)d_out;

    int M = in_sizes[1] / H;
    int J = in_sizes[2] / H;
    int N = in_sizes[3];
    if (M > MAXM) M = MAXM;
    if (J > MAXJ) J = MAXJ;

    int blocksA = (M + PREROWS - 1) / PREROWS;
    int blocksB = (J + PREROWS - 1) / PREROWS;
    k_pre<<<blocksA + blocksB + 1, H>>>(x_graph, x_m, x_job, W0, b0, M, J);

    const int smem_main =
        (8 * 32 * 36 + TILE * SAW + 16 * 4 * 4) * (int)sizeof(float);
    static int smem_set = 0;
    if (!smem_set) {
        cudaFuncSetAttribute(k_main, cudaFuncAttributeMaxDynamicSharedMemorySize,
                             smem_main);
        smem_set = 1;
    }
    k_main<<<MAIN_BLOCKS, MAIN_THREADS, smem_main>>>(m_ids, job_idx, W1, b1, W2,
                                                     N, out);
}

// round 7
// speedup vs baseline: 2.8193x; 1.2467x over previous
#include <cuda_runtime.h>
#include <cuda_bf16.h>
#include <math.h>

#define H 128
#define MAXM 2048
#define MAXJ 8192
#define MAIN_BLOCKS 296
#define MAIN_THREADS 256
#define WROWS 16                   // rows per warp
#define TILE (8 * WROWS)           // 128 ops per block-iteration
#define SAW 68                     // h0 smem row stride in 32-bit words
#define PREROWS 16

// -------- device scratch --------
__device__ float d_g[H];
__device__ float d_A[MAXM * H];
__device__ float d_B[MAXJ * H];
__device__ unsigned long long d_maxkey;
__device__ unsigned int d_ticket;
__device__ float d_blkM[MAIN_BLOCKS];
__device__ float d_blkE[MAIN_BLOCKS];
__device__ float d_blkS[MAIN_BLOCKS];

__device__ __forceinline__ unsigned int fkey(float f) {
    unsigned int b = __float_as_uint(f);
    return (b & 0x80000000u) ? ~b : (b | 0x80000000u);
}

__device__ __forceinline__ unsigned int bf2(float lo, float hi) {
    __nv_bfloat162 v = __float22bfloat162_rn(make_float2(lo, hi));
    return *(unsigned int*)&v;
}

__device__ __forceinline__ void mma_bf16(float c[4], const unsigned a[4],
                                         unsigned b0, unsigned b1) {
    asm volatile(
        "mma.sync.aligned.m16n8k16.row.col.f32.bf16.bf16.f32 "
        "{%0,%1,%2,%3}, {%4,%5,%6,%7}, {%8,%9}, {%0,%1,%2,%3};"
        : "+f"(c[0]), "+f"(c[1]), "+f"(c[2]), "+f"(c[3])
        : "r"(a[0]), "r"(a[1]), "r"(a[2]), "r"(a[3]), "r"(b0), "r"(b1));
}

__device__ __forceinline__ void osm_merge(float& m, float& se, float& ss,
                                          float m2, float se2, float ss2) {
    float M = fmaxf(m, se2 > 0.f ? m2 : m);
    if (m2 > M) M = m2;
    float a1 = (se > 0.f) ? expf(m - M) : 0.f;
    float a2 = (se2 > 0.f) ? expf(m2 - M) : 0.f;
    se = se * a1 + se2 * a2;
    ss = ss * a1 + ss2 * a2;
    m = M;
}

// ---------------- precompute: g, A = x_m@W0[2H:3H], B = x_job@W0[3H:4H] ----------------
__global__ void k_pre(const float* __restrict__ xg,
                      const float* __restrict__ xm,
                      const float* __restrict__ xj,
                      const float* __restrict__ W0,
                      const float* __restrict__ b0,
                      int M, int J) {
    const int t = threadIdx.x;
    if ((int)blockIdx.x == (int)gridDim.x - 1) {
        __shared__ float s[2 * H];
        if (t == 0) { d_maxkey = 0ull; d_ticket = 0u; }
        s[t] = xg[t];
        s[t + H] = xg[t + H];
        __syncthreads();
        float acc = b0[t];
        for (int k0 = 0; k0 < 2 * H; k0 += 8) {
            float wv[8];
#pragma unroll
            for (int u = 0; u < 8; u++) wv[u] = W0[(k0 + u) * H + t];
#pragma unroll
            for (int u = 0; u < 8; u++) acc += s[k0 + u] * wv[u];
        }
        d_g[t] = acc;
        return;
    }
    const int blocksA = (M + PREROWS - 1) / PREROWS;
    __shared__ float s[PREROWS][H];
    const float* src; float* dst;
    int row0, nrows, off;
    if ((int)blockIdx.x < blocksA) {
        row0 = blockIdx.x * PREROWS; nrows = min(PREROWS, M - row0);
        src = xm; off = 2 * H; dst = d_A;
    } else {
        row0 = ((int)blockIdx.x - blocksA) * PREROWS; nrows = min(PREROWS, J - row0);
        src = xj; off = 3 * H; dst = d_B;
    }
#pragma unroll
    for (int r = 0; r < PREROWS; r++)
        s[r][t] = (r < nrows) ? src[(row0 + r) * H + t] : 0.f;
    __syncthreads();
    float acc[PREROWS];
#pragma unroll
    for (int r = 0; r < PREROWS; r++) acc[r] = 0.f;
    const float* Wp = W0 + off * H + t;
#pragma unroll 1
    for (int k0 = 0; k0 < H; k0 += 8) {
        float wv[8];
#pragma unroll
        for (int u = 0; u < 8; u++) wv[u] = Wp[(k0 + u) * H];
#pragma unroll
        for (int u = 0; u < 8; u++) {
#pragma unroll
            for (int r = 0; r < PREROWS; r++) acc[r] += s[r][k0 + u] * wv[u];
        }
    }
    for (int r = 0; r < nrows; r++) dst[(row0 + r) * H + t] = acc[r];
}

// ---------------- main: gather + bf16 MMA layer1 + fused layer2 + softmax ----------------
__global__ void __launch_bounds__(MAIN_THREADS, 2)
k_main(const int* __restrict__ m_ids, const int* __restrict__ job_idx,
       const float* __restrict__ W1, const float* __restrict__ b1,
       const float* __restrict__ W2, int N, float* __restrict__ out) {
    extern __shared__ unsigned int smem[];
    unsigned int* W1pk = smem;                      // 8*32*36 = 9216 words
    unsigned int* h0s  = W1pk + 8 * 32 * 36;        // TILE*SAW = 8704 words
    float4* pk = (float4*)(h0s + TILE * SAW);       // 16*4 float4
    __shared__ unsigned long long wkey[MAIN_THREADS / 32];
    __shared__ float wM[MAIN_THREADS / 32], wE[MAIN_THREADS / 32], wS[MAIN_THREADS / 32];
    __shared__ int isLast;
    __shared__ double fE[MAIN_THREADS], fS[MAIN_THREADS];
    __shared__ float fM[MAIN_THREADS];

    const int t = threadIdx.x;
    const int lane = t & 31;
    const int w = t >> 5;
    const int q = lane & 3;
    const int g = lane >> 2;

    // pack W1 -> bf16x2 fragments
    for (int i = t; i < 8 * 32 * 16 * 2; i += MAIN_THREADS) {
        int c  = i & 1;
        int nt = (i >> 1) & 15;
        int ln = (i >> 5) & 31;
        int ks = (i >> 10) & 7;
        int qq = ln & 3, gg = ln >> 2;
        int k0 = 16 * ks + 2 * qq + 8 * c;
        int col = 8 * nt + gg;
        W1pk[(ks * 32 + ln) * 36 + nt * 2 + c] =
            bf2(W1[k0 * H + col], W1[(k0 + 1) * H + col]);
    }
    if (t < 64) {
        int nt = t >> 2, qq = t & 3;
        int n0 = 8 * nt + 2 * qq;
        pk[nt * 4 + qq] = make_float4(b1[n0], b1[n0 + 1], W2[n0], W2[n0 + 1]);
    }
    __syncthreads();

    const float4 g4 = *(const float4*)(d_g + 4 * lane);
    unsigned long long wmax = 0ull;
    float om = -INFINITY, ose = 0.f, oss = 0.f;

    const int T = (N + TILE - 1) / TILE;
    unsigned int* myh = h0s + (w * WROWS) * SAW;

    for (int tile = blockIdx.x; tile < T; tile += gridDim.x) {
        const int wbase = tile * TILE + w * WROWS;

        // coalesced id preload (16 ids via half the warp)
        int idrow = wbase + lane;
        int my_m = (lane < WROWS && idrow < N) ? m_ids[idrow] : 0;
        int my_j = (lane < WROWS && idrow < N) ? job_idx[idrow] : 0;

        // stage h0 = relu(g + A[m] + B[j]) as bf16x2
#pragma unroll 8
        for (int r = 0; r < WROWS; r++) {
            int m = __shfl_sync(0xffffffffu, my_m, r);
            int j = __shfl_sync(0xffffffffu, my_j, r);
            float4 h = make_float4(0.f, 0.f, 0.f, 0.f);
            if (wbase + r < N) {
                float4 a = *(const float4*)(d_A + m * H + 4 * lane);
                float4 b = *(const float4*)(d_B + j * H + 4 * lane);
                h.x = fmaxf(g4.x + a.x + b.x, 0.f);
                h.y = fmaxf(g4.y + a.y + b.y, 0.f);
                h.z = fmaxf(g4.z + a.z + b.z, 0.f);
                h.w = fmaxf(g4.w + a.w + b.w, 0.f);
            }
            uint2 u = make_uint2(bf2(h.x, h.y), bf2(h.z, h.w));
            *(uint2*)(myh + r * SAW + 2 * lane) = u;
        }
        __syncwarp();

        // layer1 bf16 MMA: 1 row-tile x 16 n-tiles, K=128 in 8 k16-steps
        float c[16][4];
#pragma unroll
        for (int nt = 0; nt < 16; nt++)
#pragma unroll
            for (int i = 0; i < 4; i++) c[nt][i] = 0.f;

#pragma unroll
        for (int ks = 0; ks < 8; ks++) {
            unsigned af[4];
            const unsigned int* ap = myh + g * SAW + 8 * ks + q;
            af[0] = ap[0];
            af[1] = ap[8 * SAW];
            af[2] = ap[4];
            af[3] = ap[8 * SAW + 4];
            const uint4* bp = (const uint4*)(W1pk + (ks * 32 + lane) * 36);
#pragma unroll
            for (int np = 0; np < 8; np++) {
                uint4 bv = bp[np];
                mma_bf16(c[2 * np],     af, bv.x, bv.y);
                mma_bf16(c[2 * np + 1], af, bv.z, bv.w);
            }
        }

        // fused layer2 + online softmax
        {
            float p0 = 0.f, p1 = 0.f;
#pragma unroll
            for (int nt = 0; nt < 16; nt++) {
                float4 v = pk[nt * 4 + q];
                p0 += fmaxf(c[nt][0] + v.x, 0.f) * v.z
                    + fmaxf(c[nt][1] + v.y, 0.f) * v.w;
                p1 += fmaxf(c[nt][2] + v.x, 0.f) * v.z
                    + fmaxf(c[nt][3] + v.y, 0.f) * v.w;
            }
            p0 += __shfl_xor_sync(0xffffffffu, p0, 1);
            p0 += __shfl_xor_sync(0xffffffffu, p0, 2);
            p1 += __shfl_xor_sync(0xffffffffu, p1, 1);
            p1 += __shfl_xor_sync(0xffffffffu, p1, 2);
            if (q == 0) {
                int r0 = wbase + g;
                if (r0 < N) {
                    unsigned long long key =
                        ((unsigned long long)fkey(p0) << 32) |
                        (unsigned long long)(~(unsigned int)r0);
                    if (key > wmax) wmax = key;
                    if (p0 > om) {
                        float cc = expf(om - p0);
                        ose = ose * cc + 1.f;
                        oss = oss * cc + p0;
                        om = p0;
                    } else {
                        float e = expf(p0 - om);
                        ose += e; oss += p0 * e;
                    }
                }
                int r1 = r0 + 8;
                if (r1 < N) {
                    unsigned long long key =
                        ((unsigned long long)fkey(p1) << 32) |
                        (unsigned long long)(~(unsigned int)r1);
                    if (key > wmax) wmax = key;
                    if (p1 > om) {
                        float cc = expf(om - p1);
                        ose = ose * cc + 1.f;
                        oss = oss * cc + p1;
                        om = p1;
                    } else {
                        float e = expf(p1 - om);
                        ose += e; oss += p1 * e;
                    }
                }
            }
        }
        __syncwarp();
    }

    // warp reduce
#pragma unroll
    for (int off = 16; off > 0; off >>= 1) {
        unsigned long long o = __shfl_xor_sync(0xffffffffu, wmax, off);
        if (o > wmax) wmax = o;
        float m2  = __shfl_xor_sync(0xffffffffu, om, off);
        float se2 = __shfl_xor_sync(0xffffffffu, ose, off);
        float ss2 = __shfl_xor_sync(0xffffffffu, oss, off);
        osm_merge(om, ose, oss, m2, se2, ss2);
    }
    if (lane == 0) { wkey[w] = wmax; wM[w] = om; wE[w] = ose; wS[w] = oss; }
    __syncthreads();
    if (t == 0) {
        unsigned long long k = wkey[0];
        float M = wM[0], E = wE[0], S = wS[0];
#pragma unroll
        for (int i = 1; i < MAIN_THREADS / 32; i++) {
            if (wkey[i] > k) k = wkey[i];
            osm_merge(M, E, S, wM[i], wE[i], wS[i]);
        }
        atomicMax(&d_maxkey, k);
        d_blkM[blockIdx.x] = M;
        d_blkE[blockIdx.x] = E;
        d_blkS[blockIdx.x] = S;
        __threadfence();
        unsigned prev = atomicAdd(&d_ticket, 1u);
        isLast = (prev == gridDim.x - 1u);
    }
    __syncthreads();

    // last block merges all block triples and writes the 4 outputs
    if (isLast) {
        float M = -INFINITY; double E = 0.0, S = 0.0;
        for (int i = t; i < (int)gridDim.x; i += MAIN_THREADS) {
            float m2 = d_blkM[i];
            double e2 = d_blkE[i], s2 = d_blkS[i];
            float Mx = fmaxf(M, (e2 > 0.0) ? m2 : M);
            if (m2 > Mx && e2 > 0.0) Mx = m2;
            double a1 = (E > 0.0) ? exp((double)(M - Mx)) : 0.0;
            double a2 = (e2 > 0.0) ? exp((double)(m2 - Mx)) : 0.0;
            E = E * a1 + e2 * a2;
            S = S * a1 + s2 * a2;
            M = Mx;
        }
        fM[t] = M; fE[t] = E; fS[t] = S;
        __syncthreads();
        for (int o = MAIN_THREADS / 2; o > 0; o >>= 1) {
            if (t < o) {
                float m1 = fM[t], m2 = fM[t + o];
                double e1 = fE[t], e2 = fE[t + o];
                double s1 = fS[t], s2 = fS[t + o];
                float Mx = fmaxf((e1 > 0.0) ? m1 : -INFINITY,
                                 (e2 > 0.0) ? m2 : -INFINITY);
                double a1 = (e1 > 0.0) ? exp((double)(m1 - Mx)) : 0.0;
                double a2 = (e2 > 0.0) ? exp((double)(m2 - Mx)) : 0.0;
                fM[t] = Mx;
                fE[t] = e1 * a1 + e2 * a2;
                fS[t] = s1 * a1 + s2 * a2;
            }
            __syncthreads();
        }
        if (t == 0) {
            unsigned long long key = d_maxkey;
            unsigned int idx = ~(unsigned int)(key & 0xffffffffu);
            double sumexp = fE[0];
            double sums = fS[0];
            double lg = log(sumexp);
            out[0] = (float)idx;
            out[1] = (float)(1.0 / sumexp);
            out[2] = (float)(-lg);
            out[3] = (float)((double)fM[0] + lg - sums / sumexp);
        }
    }
}

extern "C" void kernel_launch(void* const* d_in, const int* in_sizes, int n_in,
                              void* d_out, int out_size) {
    const float* x_graph = (const float*)d_in[0];
    const float* x_m     = (const float*)d_in[1];
    const float* x_job   = (const float*)d_in[2];
    const int*   m_ids   = (const int*)d_in[3];
    const int*   job_idx = (const int*)d_in[4];
    const float* W0      = (const float*)d_in[5];
    const float* b0      = (const float*)d_in[6];
    const float* W1      = (const float*)d_in[7];
    const float* b1      = (const float*)d_in[8];
    const float* W2      = (const float*)d_in[9];
    float* out = (float*)d_out;

    int M = in_sizes[1] / H;
    int J = in_sizes[2] / H;
    int N = in_sizes[3];
    if (M > MAXM) M = MAXM;
    if (J > MAXJ) J = MAXJ;

    int blocksA = (M + PREROWS - 1) / PREROWS;
    int blocksB = (J + PREROWS - 1) / PREROWS;
    k_pre<<<blocksA + blocksB + 1, H>>>(x_graph, x_m, x_job, W0, b0, M, J);

    const int smem_main =
        (8 * 32 * 36 + TILE * SAW + 16 * 4 * 4) * (int)sizeof(float);
    static int smem_set = 0;
    if (!smem_set) {
        cudaFuncSetAttribute(k_main, cudaFuncAttributeMaxDynamicSharedMemorySize,
                             smem_main);
        smem_set = 1;
    }
    k_main<<<MAIN_BLOCKS, MAIN_THREADS, smem_main>>>(m_ids, job_idx, W1, b1, W2,
                                                     N, out);
}